// round 1
// baseline (speedup 1.0000x reference)
#include <cuda_runtime.h>
#include <math.h>

#define NN 50000
#define EE 800000
#define ETOT 850000        // EE + NN self loops
#define FIN 128
#define HIDC 32
#define HEADS 8
#define NG 64
#define F1 256             // HEADS*HIDC
#define FULLMASK 0xffffffffu

// ---------------- scratch (static device memory; no allocs allowed) ----------
__device__ float g_h1[(size_t)NN * F1];      // x @ W1           [N,256]
__device__ float g_out1[(size_t)NN * F1];    // relu(gat1)+b1    [N,256]
__device__ float g_h2[(size_t)NN * HIDC];    // out1 @ W2        [N,32]
__device__ float g_out2[(size_t)NN * HIDC];  // gat2 + b2        [N,32]
__device__ float g_als1[NN * HEADS];
__device__ float g_ald1[NN * HEADS];
__device__ float g_als2[NN];
__device__ float g_ald2[NN];
__device__ int   g_deg[NN];
__device__ int   g_rowptr[NN + 1];
__device__ int   g_cursor[NN];
__device__ int   g_srcs[ETOT];
__device__ float g_sums[NG * HIDC];
__device__ int   g_cnts[NG];

// ---------------- small utility kernels --------------------------------------
__global__ void zero_kernel() {
    int i = blockIdx.x * blockDim.x + threadIdx.x;
    if (i < NN) g_deg[i] = 0;
    if (i < NG * HIDC) g_sums[i] = 0.0f;
    if (i < NG) g_cnts[i] = 0;
}

__global__ void deg_kernel(const int* __restrict__ ei) {
    int i = blockIdx.x * blockDim.x + threadIdx.x;
    if (i >= ETOT) return;
    int dst = (i < EE) ? ei[EE + i] : (i - EE);
    atomicAdd(&g_deg[dst], 1);
}

// one-block prefix sum (warp shuffles + 32-wide smem combine)
__global__ void scan_kernel() {
    __shared__ int warpsum[32];
    __shared__ int s_running;
    int tid = threadIdx.x, lane = tid & 31, wid = tid >> 5;
    if (tid == 0) { s_running = 0; g_rowptr[0] = 0; }
    __syncthreads();
    for (int base = 0; base < NN; base += 1024) {
        int i = base + tid;
        int v = (i < NN) ? g_deg[i] : 0;
        int x = v;
        #pragma unroll
        for (int off = 1; off < 32; off <<= 1) {
            int t = __shfl_up_sync(FULLMASK, x, off);
            if (lane >= off) x += t;
        }
        if (lane == 31) warpsum[wid] = x;
        __syncthreads();
        if (wid == 0) {
            int w = warpsum[lane];
            #pragma unroll
            for (int off = 1; off < 32; off <<= 1) {
                int t = __shfl_up_sync(FULLMASK, w, off);
                if (lane >= off) w += t;
            }
            warpsum[lane] = w;
        }
        __syncthreads();
        int offset = s_running + (wid > 0 ? warpsum[wid - 1] : 0);
        int incl = offset + x;
        if (i < NN) { g_rowptr[i + 1] = incl; g_cursor[i] = incl - v; }
        __syncthreads();
        if (tid == 0) s_running += warpsum[31];
        __syncthreads();
    }
}

__global__ void fill_kernel(const int* __restrict__ ei) {
    int i = blockIdx.x * blockDim.x + threadIdx.x;
    if (i >= ETOT) return;
    int src, dst;
    if (i < EE) { src = ei[i]; dst = ei[EE + i]; }
    else        { src = i - EE; dst = i - EE; }
    int pos = atomicAdd(&g_cursor[dst], 1);
    g_srcs[pos] = src;
}

// ---------------- SGEMM (register-tiled, fp32) -------------------------------
// MODE 1: C=g_h1 <- Aparam(x) @ B(W1).  MODE 2: C=g_h2 <- g_out1 @ B(W2).
template <int BM, int BN, int BK, int TM, int TN, int MODE>
__global__ void sgemm(const float* __restrict__ Aparam, const float* __restrict__ B,
                      int M, int N, int K) {
    constexpr int THREADS = (BM / TM) * (BN / TN);
    const float* A = (MODE == 1) ? Aparam : g_out1;
    float* C = (MODE == 1) ? g_h1 : g_h2;

    __shared__ float As[BK][BM];
    __shared__ float Bs[BK][BN];
    int tid = threadIdx.x;
    int tx = tid % (BN / TN);
    int ty = tid / (BN / TN);
    int row0 = blockIdx.y * BM;
    int col0 = blockIdx.x * BN;

    float acc[TM][TN];
    #pragma unroll
    for (int i = 0; i < TM; i++)
        #pragma unroll
        for (int j = 0; j < TN; j++) acc[i][j] = 0.0f;

    for (int k0 = 0; k0 < K; k0 += BK) {
        // A tile (BM x BK) -> As[k][m] (transposed)
        #pragma unroll
        for (int idx = tid * 4; idx < BM * BK; idx += THREADS * 4) {
            int r = idx / BK, c = idx % BK;
            float4 v = make_float4(0.f, 0.f, 0.f, 0.f);
            if (row0 + r < M)
                v = *reinterpret_cast<const float4*>(A + (size_t)(row0 + r) * K + k0 + c);
            As[c + 0][r] = v.x; As[c + 1][r] = v.y; As[c + 2][r] = v.z; As[c + 3][r] = v.w;
        }
        // B tile (BK x BN)
        #pragma unroll
        for (int idx = tid * 4; idx < BK * BN; idx += THREADS * 4) {
            int r = idx / BN, c = idx % BN;
            float4 v = *reinterpret_cast<const float4*>(B + (size_t)(k0 + r) * N + col0 + c);
            *reinterpret_cast<float4*>(&Bs[r][c]) = v;
        }
        __syncthreads();
        #pragma unroll
        for (int k = 0; k < BK; k++) {
            float4 a4 = *reinterpret_cast<const float4*>(&As[k][ty * TM]);
            float4 b4 = *reinterpret_cast<const float4*>(&Bs[k][tx * TN]);
            float a[4] = {a4.x, a4.y, a4.z, a4.w};
            float b[4] = {b4.x, b4.y, b4.z, b4.w};
            #pragma unroll
            for (int i = 0; i < TM; i++)
                #pragma unroll
                for (int j = 0; j < TN; j++) acc[i][j] += a[i] * b[j];
        }
        __syncthreads();
    }
    #pragma unroll
    for (int i = 0; i < TM; i++) {
        int r = row0 + ty * TM + i;
        if (r < M) {
            #pragma unroll
            for (int j = 0; j < TN; j++)
                C[(size_t)r * N + col0 + tx * TN + j] = acc[i][j];
        }
    }
}

// ---------------- attention logit projections --------------------------------
template <int LAYER>
__global__ void al_kernel(const float* __restrict__ asrc, const float* __restrict__ adst) {
    constexpr int H = (LAYER == 1) ? HEADS : 1;
    const float* hf = (LAYER == 1) ? g_h1 : g_h2;
    float* als = (LAYER == 1) ? g_als1 : g_als2;
    float* ald = (LAYER == 1) ? g_ald1 : g_ald2;
    int w = (blockIdx.x * blockDim.x + threadIdx.x) >> 5;
    int lane = threadIdx.x & 31;
    if (w >= NN) return;
    #pragma unroll
    for (int h = 0; h < H; h++) {
        float v = hf[(size_t)w * (H * HIDC) + h * HIDC + lane];
        float ps = v * asrc[h * HIDC + lane];
        float pd = v * adst[h * HIDC + lane];
        #pragma unroll
        for (int off = 16; off; off >>= 1) {
            ps += __shfl_down_sync(FULLMASK, ps, off);
            pd += __shfl_down_sync(FULLMASK, pd, off);
        }
        if (lane == 0) { als[w * H + h] = ps; ald[w * H + h] = pd; }
    }
}

// ---------------- GAT attention + aggregation (gather form, warp per node) ---
template <int LAYER>
__global__ void atten_kernel(const float* __restrict__ bias) {
    constexpr int H = (LAYER == 1) ? HEADS : 1;
    const float* hf = (LAYER == 1) ? g_h1 : g_h2;
    const float* als = (LAYER == 1) ? g_als1 : g_als2;
    const float* ald = (LAYER == 1) ? g_ald1 : g_ald2;
    float* outp = (LAYER == 1) ? g_out1 : g_out2;

    int node = (blockIdx.x * blockDim.x + threadIdx.x) >> 5;
    int lane = threadIdx.x & 31;
    if (node >= NN) return;

    int start = g_rowptr[node], end = g_rowptr[node + 1];

    float ad[H];
    #pragma unroll
    for (int h = 0; h < H; h++) ad[h] = ald[node * H + h];

    // phase 1: online softmax stats (max + sum), edges strided across lanes
    float m[H], z[H];
    #pragma unroll
    for (int h = 0; h < H; h++) { m[h] = -INFINITY; z[h] = 0.0f; }

    for (int i = start + lane; i < end; i += 32) {
        int s = g_srcs[i];
        const float* asv = als + (size_t)s * H;
        #pragma unroll
        for (int h = 0; h < H; h++) {
            float e = asv[h] + ad[h];
            e = (e > 0.0f) ? e : 0.2f * e;
            float mn = fmaxf(m[h], e);
            z[h] = z[h] * __expf(m[h] - mn) + __expf(e - mn);
            m[h] = mn;
        }
    }
    // warp combine (guard NaN from -inf - -inf)
    #pragma unroll
    for (int off = 16; off; off >>= 1) {
        #pragma unroll
        for (int h = 0; h < H; h++) {
            float mo = __shfl_down_sync(FULLMASK, m[h], off);
            float zo = __shfl_down_sync(FULLMASK, z[h], off);
            float mn = fmaxf(m[h], mo);
            float za = (m[h] != -INFINITY) ? z[h] * __expf(m[h] - mn) : 0.0f;
            float zb = (mo   != -INFINITY) ? zo   * __expf(mo   - mn) : 0.0f;
            m[h] = mn; z[h] = za + zb;
        }
    }
    float invz[H];
    #pragma unroll
    for (int h = 0; h < H; h++) {
        m[h] = __shfl_sync(FULLMASK, m[h], 0);
        z[h] = __shfl_sync(FULLMASK, z[h], 0);
        invz[h] = 1.0f / z[h];   // deg >= 1 (self loop) => z > 0
    }

    // phase 2: weighted gather-accumulate; lane owns column `lane` of each head
    float acc[H];
    #pragma unroll
    for (int h = 0; h < H; h++) acc[h] = 0.0f;

    for (int i = start; i < end; i++) {
        int s = g_srcs[i];
        const float* asv = als + (size_t)s * H;
        const float* hv = hf + (size_t)s * (H * HIDC);
        #pragma unroll
        for (int h = 0; h < H; h++) {
            float e = asv[h] + ad[h];
            e = (e > 0.0f) ? e : 0.2f * e;
            float alpha = __expf(e - m[h]) * invz[h];
            acc[h] += alpha * hv[h * HIDC + lane];
        }
    }
    #pragma unroll
    for (int h = 0; h < H; h++) {
        float v = acc[h] + bias[h * HIDC + lane];
        if (LAYER == 1) v = fmaxf(v, 0.0f);
        outp[(size_t)node * (H * HIDC) + h * HIDC + lane] = v;
    }
}

// ---------------- pooling ----------------------------------------------------
__global__ void pool_kernel(const int* __restrict__ batch) {
    int w = (blockIdx.x * blockDim.x + threadIdx.x) >> 5;
    int lane = threadIdx.x & 31;
    if (w >= NN) return;
    int g = batch[w];
    atomicAdd(&g_sums[g * HIDC + lane], g_out2[(size_t)w * HIDC + lane]);
    if (lane == 0) atomicAdd(&g_cnts[g], 1);
}

__global__ void div_kernel(float* __restrict__ out) {
    int i = blockIdx.x * blockDim.x + threadIdx.x;
    if (i < NG * HIDC)
        out[i] = g_sums[i] / fmaxf((float)g_cnts[i / HIDC], 1.0f);
}

// ---------------- launch -----------------------------------------------------
extern "C" void kernel_launch(void* const* d_in, const int* in_sizes, int n_in,
                              void* d_out, int out_size) {
    const float* x   = (const float*)d_in[0];
    const int*   ei  = (const int*)d_in[1];
    // d_in[2] edge_attr: unused by reference (lin_edge=None)
    const int* batch = (const int*)d_in[3];
    const float* W1  = (const float*)d_in[4];
    const float* as1 = (const float*)d_in[5];
    const float* ad1 = (const float*)d_in[6];
    const float* b1  = (const float*)d_in[7];
    const float* W2  = (const float*)d_in[8];
    const float* as2 = (const float*)d_in[9];
    const float* ad2 = (const float*)d_in[10];
    const float* b2  = (const float*)d_in[11];
    float* out = (float*)d_out;

    const int WB = (NN * 32 + 255) / 256;   // warp-per-node grids (6250)

    zero_kernel<<<(NN + 255) / 256, 256>>>();
    deg_kernel<<<(ETOT + 255) / 256, 256>>>(ei);
    scan_kernel<<<1, 1024>>>();
    fill_kernel<<<(ETOT + 255) / 256, 256>>>(ei);

    sgemm<64, 64, 16, 4, 4, 1><<<dim3(F1 / 64, (NN + 63) / 64), 256>>>(x, W1, NN, F1, FIN);
    al_kernel<1><<<WB, 256>>>(as1, ad1);
    atten_kernel<1><<<WB, 256>>>(b1);

    sgemm<64, 32, 32, 4, 4, 2><<<dim3(1, (NN + 63) / 64), 128>>>(nullptr, W2, NN, HIDC, F1);
    al_kernel<2><<<WB, 256>>>(as2, ad2);
    atten_kernel<2><<<WB, 256>>>(b2);

    pool_kernel<<<WB, 256>>>(batch);
    div_kernel<<<(NG * HIDC + 255) / 256, 256>>>(out);
}

// round 2
// speedup vs baseline: 1.9155x; 1.9155x over previous
#include <cuda_runtime.h>
#include <cuda_fp16.h>
#include <math.h>

#define NN 50000
#define EE 800000
#define ETOT 850000        // EE + NN self loops
#define FIN 128
#define HIDC 32
#define HEADS 8
#define NG 64
#define F1 256             // HEADS*HIDC
#define FULLMASK 0xffffffffu
#define NB_SCAN ((NN + 1023) / 1024)   // 49

// ---------------- scratch (static device memory; no allocs allowed) ----------
__device__ float  g_h1[(size_t)NN * F1];      // x @ W1           [N,256]
__device__ __half g_h1h[(size_t)NN * F1];     // fp16 shadow of h1 for gather
__device__ float  g_out1[(size_t)NN * F1];    // relu(gat1)+b1    [N,256]
__device__ float  g_h2[(size_t)NN * HIDC];    // out1 @ W2        [N,32]
__device__ float  g_out2[(size_t)NN * HIDC];  // gat2 + b2        [N,32]
__device__ float  g_als1[NN * HEADS];
__device__ float  g_ald1[NN * HEADS];
__device__ float  g_als2[NN];
__device__ float  g_ald2[NN];
__device__ int    g_deg[NN];
__device__ int    g_rowptr[NN + 1];
__device__ int    g_cursor[NN];
__device__ int    g_srcs[ETOT];
__device__ int    g_bsum[NB_SCAN];
__device__ int    g_boff[NB_SCAN];
__device__ float  g_sums[NG * HIDC];
__device__ int    g_cnts[NG];

// ---------------- small utility kernels --------------------------------------
__global__ void zero_kernel() {
    int i = blockIdx.x * blockDim.x + threadIdx.x;
    if (i < NN) g_deg[i] = 0;
    if (i < NG * HIDC) g_sums[i] = 0.0f;
    if (i < NG) g_cnts[i] = 0;
}

__global__ void deg_kernel(const int* __restrict__ ei) {
    int i = blockIdx.x * blockDim.x + threadIdx.x;
    if (i >= ETOT) return;
    int dst = (i < EE) ? ei[EE + i] : (i - EE);
    atomicAdd(&g_deg[dst], 1);
}

// ---- 3-kernel scan: block-local scan, scan of partials, apply ----------------
__global__ void scan_blocks() {
    __shared__ int ws[32];
    int b = blockIdx.x, tid = threadIdx.x, lane = tid & 31, wid = tid >> 5;
    int i = b * 1024 + tid;
    int v = (i < NN) ? g_deg[i] : 0;
    int x = v;
    #pragma unroll
    for (int o = 1; o < 32; o <<= 1) { int t = __shfl_up_sync(FULLMASK, x, o); if (lane >= o) x += t; }
    if (lane == 31) ws[wid] = x;
    __syncthreads();
    if (wid == 0) {
        int w = ws[lane];
        #pragma unroll
        for (int o = 1; o < 32; o <<= 1) { int t = __shfl_up_sync(FULLMASK, w, o); if (lane >= o) w += t; }
        ws[lane] = w;
    }
    __syncthreads();
    int incl = x + (wid ? ws[wid - 1] : 0);
    if (i < NN) g_rowptr[i + 1] = incl;     // block-local inclusive
    if (tid == 1023) g_bsum[b] = incl;
}

__global__ void scan_sums() {   // 1 block, 32 threads
    int lane = threadIdx.x;
    int run = 0;
    for (int base = 0; base < NB_SCAN; base += 32) {
        int idx = base + lane;
        int v = (idx < NB_SCAN) ? g_bsum[idx] : 0;
        int x = v;
        #pragma unroll
        for (int o = 1; o < 32; o <<= 1) { int t = __shfl_up_sync(FULLMASK, x, o); if (lane >= o) x += t; }
        if (idx < NB_SCAN) g_boff[idx] = run + x - v;   // exclusive
        run += __shfl_sync(FULLMASK, x, 31);
    }
}

__global__ void scan_apply() {
    int i = blockIdx.x * blockDim.x + threadIdx.x;
    if (i == 0) g_rowptr[0] = 0;
    if (i < NN) {
        int r = g_rowptr[i + 1] + g_boff[i >> 10];
        g_rowptr[i + 1] = r;
        g_cursor[i] = r - g_deg[i];
    }
}

__global__ void fill_kernel(const int* __restrict__ ei) {
    int i = blockIdx.x * blockDim.x + threadIdx.x;
    if (i >= ETOT) return;
    int src, dst;
    if (i < EE) { src = ei[i]; dst = ei[EE + i]; }
    else        { src = i - EE; dst = i - EE; }
    int pos = atomicAdd(&g_cursor[dst], 1);
    g_srcs[pos] = src;
}

// ---------------- SGEMM (register-tiled, fp32) -------------------------------
// MODE 1: C=g_h1 <- Aparam(x) @ B(W1).  MODE 2: C=g_h2 <- g_out1 @ B(W2).
template <int BM, int BN, int BK, int TM, int TN, int MODE>
__global__ void sgemm(const float* __restrict__ Aparam, const float* __restrict__ B,
                      int M, int N, int K) {
    constexpr int THREADS = (BM / TM) * (BN / TN);
    const float* A = (MODE == 1) ? Aparam : g_out1;
    float* C = (MODE == 1) ? g_h1 : g_h2;

    __shared__ float As[BK][BM];
    __shared__ float Bs[BK][BN];
    int tid = threadIdx.x;
    int tx = tid % (BN / TN);
    int ty = tid / (BN / TN);
    int row0 = blockIdx.y * BM;
    int col0 = blockIdx.x * BN;

    float acc[TM][TN];
    #pragma unroll
    for (int i = 0; i < TM; i++)
        #pragma unroll
        for (int j = 0; j < TN; j++) acc[i][j] = 0.0f;

    for (int k0 = 0; k0 < K; k0 += BK) {
        #pragma unroll
        for (int idx = tid * 4; idx < BM * BK; idx += THREADS * 4) {
            int r = idx / BK, c = idx % BK;
            float4 v = make_float4(0.f, 0.f, 0.f, 0.f);
            if (row0 + r < M)
                v = *reinterpret_cast<const float4*>(A + (size_t)(row0 + r) * K + k0 + c);
            As[c + 0][r] = v.x; As[c + 1][r] = v.y; As[c + 2][r] = v.z; As[c + 3][r] = v.w;
        }
        #pragma unroll
        for (int idx = tid * 4; idx < BK * BN; idx += THREADS * 4) {
            int r = idx / BN, c = idx % BN;
            float4 v = *reinterpret_cast<const float4*>(B + (size_t)(k0 + r) * N + col0 + c);
            *reinterpret_cast<float4*>(&Bs[r][c]) = v;
        }
        __syncthreads();
        #pragma unroll
        for (int k = 0; k < BK; k++) {
            float a[TM], b[TN];
            #pragma unroll
            for (int i = 0; i < TM; i += 4) {
                float4 t = *reinterpret_cast<const float4*>(&As[k][ty * TM + i]);
                a[i] = t.x; a[i + 1] = t.y; a[i + 2] = t.z; a[i + 3] = t.w;
            }
            #pragma unroll
            for (int j = 0; j < TN; j += 4) {
                float4 t = *reinterpret_cast<const float4*>(&Bs[k][tx * TN + j]);
                b[j] = t.x; b[j + 1] = t.y; b[j + 2] = t.z; b[j + 3] = t.w;
            }
            #pragma unroll
            for (int i = 0; i < TM; i++)
                #pragma unroll
                for (int j = 0; j < TN; j++) acc[i][j] += a[i] * b[j];
        }
        __syncthreads();
    }
    #pragma unroll
    for (int i = 0; i < TM; i++) {
        int r = row0 + ty * TM + i;
        if (r < M) {
            #pragma unroll
            for (int j = 0; j < TN; j++)
                C[(size_t)r * N + col0 + tx * TN + j] = acc[i][j];
        }
    }
}

// ---------------- attention logit projections (+fp16 shadow for layer 1) -----
template <int LAYER>
__global__ void al_kernel(const float* __restrict__ asrc, const float* __restrict__ adst) {
    constexpr int H = (LAYER == 1) ? HEADS : 1;
    const float* hf = (LAYER == 1) ? g_h1 : g_h2;
    float* als = (LAYER == 1) ? g_als1 : g_als2;
    float* ald = (LAYER == 1) ? g_ald1 : g_ald2;
    int w = (blockIdx.x * blockDim.x + threadIdx.x) >> 5;
    int lane = threadIdx.x & 31;
    if (w >= NN) return;
    #pragma unroll
    for (int h = 0; h < H; h++) {
        float v = hf[(size_t)w * (H * HIDC) + h * HIDC + lane];
        if (LAYER == 1) g_h1h[(size_t)w * F1 + h * HIDC + lane] = __float2half(v);
        float ps = v * asrc[h * HIDC + lane];
        float pd = v * adst[h * HIDC + lane];
        #pragma unroll
        for (int off = 16; off; off >>= 1) {
            ps += __shfl_down_sync(FULLMASK, ps, off);
            pd += __shfl_down_sync(FULLMASK, pd, off);
        }
        if (lane == 0) { als[w * H + h] = ps; ald[w * H + h] = pd; }
    }
}

// ---------------- GAT layer 1: warp/node, smem alphas, fp16 gather -----------
__global__ void atten1_kernel(const float* __restrict__ bias) {
    __shared__ float s_alpha[8][32][9];   // [warp][edge-in-chunk][head] padded
    int node = (blockIdx.x * blockDim.x + threadIdx.x) >> 5;
    int lane = threadIdx.x & 31;
    int warp = (threadIdx.x >> 5) & 7;
    if (node >= NN) return;
    int start = g_rowptr[node], end = g_rowptr[node + 1];

    float ad[8];
    #pragma unroll
    for (int h = 0; h < 8; h++) ad[h] = g_ald1[node * 8 + h];

    // phase 1: online softmax stats, edges strided across lanes
    float m[8], z[8];
    #pragma unroll
    for (int h = 0; h < 8; h++) { m[h] = -INFINITY; z[h] = 0.0f; }
    for (int i = start + lane; i < end; i += 32) {
        int s = g_srcs[i];
        float4 a0 = *reinterpret_cast<const float4*>(g_als1 + (size_t)s * 8);
        float4 a1 = *reinterpret_cast<const float4*>(g_als1 + (size_t)s * 8 + 4);
        float av[8] = {a0.x, a0.y, a0.z, a0.w, a1.x, a1.y, a1.z, a1.w};
        #pragma unroll
        for (int h = 0; h < 8; h++) {
            float e = av[h] + ad[h];
            e = (e > 0.0f) ? e : 0.2f * e;
            float mn = fmaxf(m[h], e);
            z[h] = z[h] * __expf(m[h] - mn) + __expf(e - mn);
            m[h] = mn;
        }
    }
    #pragma unroll
    for (int off = 16; off; off >>= 1) {
        #pragma unroll
        for (int h = 0; h < 8; h++) {
            float mo = __shfl_down_sync(FULLMASK, m[h], off);
            float zo = __shfl_down_sync(FULLMASK, z[h], off);
            float mn = fmaxf(m[h], mo);
            float za = (m[h] != -INFINITY) ? z[h] * __expf(m[h] - mn) : 0.0f;
            float zb = (mo   != -INFINITY) ? zo   * __expf(mo   - mn) : 0.0f;
            m[h] = mn; z[h] = za + zb;
        }
    }
    float invz[8];
    #pragma unroll
    for (int h = 0; h < 8; h++) {
        m[h] = __shfl_sync(FULLMASK, m[h], 0);
        invz[h] = 1.0f / __shfl_sync(FULLMASK, z[h], 0);
    }

    // phase 2: chunked gather. lane owns half2 column pair; 2 heads per p.
    int hsel = lane >> 4;
    float2 acc[4];
    #pragma unroll
    for (int p = 0; p < 4; p++) acc[p] = make_float2(0.f, 0.f);
    const __half2* hbase = reinterpret_cast<const __half2*>(g_h1h);

    for (int i = start; i < end; i += 32) {
        int cnt = min(32, end - i);
        int sreg = (lane < cnt) ? g_srcs[i + lane] : 0;
        if (lane < cnt) {
            float4 a0 = *reinterpret_cast<const float4*>(g_als1 + (size_t)sreg * 8);
            float4 a1 = *reinterpret_cast<const float4*>(g_als1 + (size_t)sreg * 8 + 4);
            float av[8] = {a0.x, a0.y, a0.z, a0.w, a1.x, a1.y, a1.z, a1.w};
            #pragma unroll
            for (int h = 0; h < 8; h++) {
                float e = av[h] + ad[h];
                e = (e > 0.0f) ? e : 0.2f * e;
                s_alpha[warp][lane][h] = __expf(e - m[h]) * invz[h];
            }
        }
        __syncwarp();
        for (int j = 0; j < cnt; j++) {
            int s = __shfl_sync(FULLMASK, sreg, j);
            const __half2* hv = hbase + (size_t)s * 128 + lane;
            #pragma unroll
            for (int p = 0; p < 4; p++) {
                float alpha = s_alpha[warp][j][2 * p + hsel];
                float2 f = __half22float2(hv[p * 32]);
                acc[p].x += alpha * f.x;
                acc[p].y += alpha * f.y;
            }
        }
        __syncwarp();
    }
    #pragma unroll
    for (int p = 0; p < 4; p++) {
        int c = p * 64 + 2 * lane;
        float vx = fmaxf(acc[p].x + bias[c], 0.0f);
        float vy = fmaxf(acc[p].y + bias[c + 1], 0.0f);
        *reinterpret_cast<float2*>(&g_out1[(size_t)node * F1 + c]) = make_float2(vx, vy);
    }
}

// ---------------- GAT layer 2 (H=1, fp32 gather) -----------------------------
__global__ void atten2_kernel(const float* __restrict__ bias) {
    __shared__ float s_alpha[8][32];
    int node = (blockIdx.x * blockDim.x + threadIdx.x) >> 5;
    int lane = threadIdx.x & 31;
    int warp = (threadIdx.x >> 5) & 7;
    if (node >= NN) return;
    int start = g_rowptr[node], end = g_rowptr[node + 1];
    float ad = g_ald2[node];

    float m = -INFINITY, z = 0.0f;
    for (int i = start + lane; i < end; i += 32) {
        float e = g_als2[g_srcs[i]] + ad;
        e = (e > 0.0f) ? e : 0.2f * e;
        float mn = fmaxf(m, e);
        z = z * __expf(m - mn) + __expf(e - mn);
        m = mn;
    }
    #pragma unroll
    for (int off = 16; off; off >>= 1) {
        float mo = __shfl_down_sync(FULLMASK, m, off);
        float zo = __shfl_down_sync(FULLMASK, z, off);
        float mn = fmaxf(m, mo);
        float za = (m  != -INFINITY) ? z  * __expf(m  - mn) : 0.0f;
        float zb = (mo != -INFINITY) ? zo * __expf(mo - mn) : 0.0f;
        m = mn; z = za + zb;
    }
    m = __shfl_sync(FULLMASK, m, 0);
    float invz = 1.0f / __shfl_sync(FULLMASK, z, 0);

    float acc = 0.0f;
    for (int i = start; i < end; i += 32) {
        int cnt = min(32, end - i);
        int sreg = (lane < cnt) ? g_srcs[i + lane] : 0;
        if (lane < cnt) {
            float e = g_als2[sreg] + ad;
            e = (e > 0.0f) ? e : 0.2f * e;
            s_alpha[warp][lane] = __expf(e - m) * invz;
        }
        __syncwarp();
        for (int j = 0; j < cnt; j++) {
            int s = __shfl_sync(FULLMASK, sreg, j);
            acc += s_alpha[warp][j] * g_h2[(size_t)s * HIDC + lane];
        }
        __syncwarp();
    }
    g_out2[(size_t)node * HIDC + lane] = acc + bias[lane];
}

// ---------------- pooling ----------------------------------------------------
__global__ void pool_kernel(const int* __restrict__ batch) {
    int w = (blockIdx.x * blockDim.x + threadIdx.x) >> 5;
    int lane = threadIdx.x & 31;
    if (w >= NN) return;
    int g = batch[w];
    atomicAdd(&g_sums[g * HIDC + lane], g_out2[(size_t)w * HIDC + lane]);
    if (lane == 0) atomicAdd(&g_cnts[g], 1);
}

__global__ void div_kernel(float* __restrict__ out) {
    int i = blockIdx.x * blockDim.x + threadIdx.x;
    if (i < NG * HIDC)
        out[i] = g_sums[i] / fmaxf((float)g_cnts[i / HIDC], 1.0f);
}

// ---------------- launch -----------------------------------------------------
extern "C" void kernel_launch(void* const* d_in, const int* in_sizes, int n_in,
                              void* d_out, int out_size) {
    const float* x   = (const float*)d_in[0];
    const int*   ei  = (const int*)d_in[1];
    // d_in[2] edge_attr: unused by reference (lin_edge=None)
    const int* batch = (const int*)d_in[3];
    const float* W1  = (const float*)d_in[4];
    const float* as1 = (const float*)d_in[5];
    const float* ad1 = (const float*)d_in[6];
    const float* b1  = (const float*)d_in[7];
    const float* W2  = (const float*)d_in[8];
    const float* as2 = (const float*)d_in[9];
    const float* ad2 = (const float*)d_in[10];
    const float* b2  = (const float*)d_in[11];
    float* out = (float*)d_out;

    const int WB = (NN * 32 + 255) / 256;   // warp-per-node grids (6250)

    zero_kernel<<<(NN + 255) / 256, 256>>>();
    deg_kernel<<<(ETOT + 255) / 256, 256>>>(ei);
    scan_blocks<<<NB_SCAN, 1024>>>();
    scan_sums<<<1, 32>>>();
    scan_apply<<<(NN + 255) / 256, 256>>>();
    fill_kernel<<<(ETOT + 255) / 256, 256>>>(ei);

    sgemm<128, 64, 16, 8, 4, 1><<<dim3(F1 / 64, (NN + 127) / 128), 256>>>(x, W1, NN, F1, FIN);
    al_kernel<1><<<WB, 256>>>(as1, ad1);
    atten1_kernel<<<WB, 256>>>(b1);

    sgemm<128, 32, 32, 8, 4, 2><<<dim3(1, (NN + 127) / 128), 128>>>(nullptr, W2, NN, HIDC, F1);
    al_kernel<2><<<WB, 256>>>(as2, ad2);
    atten2_kernel<<<WB, 256>>>(b2);

    pool_kernel<<<WB, 256>>>(batch);
    div_kernel<<<(NG * HIDC + 255) / 256, 256>>>(out);
}

// round 3
// speedup vs baseline: 2.1378x; 1.1160x over previous
#include <cuda_runtime.h>
#include <cuda_fp16.h>
#include <mma.h>
#include <math.h>

using namespace nvcuda;

#define NN 50000
#define NPAD 50048         // 391 * 128, wmma-store padded
#define EE 800000
#define ETOT 850000        // EE + NN self loops
#define FIN 128
#define HIDC 32
#define HEADS 8
#define NG 64
#define F1 256             // HEADS*HIDC
#define FULLMASK 0xffffffffu
#define NB_SCAN ((NN + 1023) / 1024)   // 49

// ---------------- scratch (static device memory; no allocs allowed) ----------
__device__ float  g_h1[(size_t)NPAD * F1];     // x @ W1           [Npad,256]
__device__ __half g_h1h[(size_t)NN * F1];      // fp16 shadow of h1 for gather
__device__ float  g_out1[(size_t)NPAD * F1];   // relu(gat1)+b1    [Npad,256]
__device__ float  g_h2[(size_t)NPAD * HIDC];   // out1 @ W2        [Npad,32]
__device__ float  g_out2[(size_t)NN * HIDC];   // gat2 + b2        [N,32]
__device__ float  g_als1[NN * HEADS];
__device__ float  g_ald1[NN * HEADS];
__device__ float  g_als2[NN];
__device__ float  g_ald2[NN];
__device__ int    g_deg[NN];
__device__ int    g_rowptr[NN + 1];
__device__ int    g_cursor[NN];
__device__ int    g_srcs[ETOT];
__device__ int    g_bsum[NB_SCAN];
__device__ int    g_boff[NB_SCAN];
__device__ float  g_sums[NG * HIDC];
__device__ int    g_cnts[NG];

// ---------------- small utility kernels --------------------------------------
__global__ void zero_kernel() {
    int i = blockIdx.x * blockDim.x + threadIdx.x;
    if (i < NN) g_deg[i] = 0;
    if (i < NG * HIDC) g_sums[i] = 0.0f;
    if (i < NG) g_cnts[i] = 0;
}

__global__ void deg_kernel(const int* __restrict__ ei) {
    int i = blockIdx.x * blockDim.x + threadIdx.x;
    if (i >= ETOT) return;
    int dst = (i < EE) ? ei[EE + i] : (i - EE);
    atomicAdd(&g_deg[dst], 1);
}

// ---- 3-kernel scan: block-local scan, scan of partials, apply ----------------
__global__ void scan_blocks() {
    __shared__ int ws[32];
    int b = blockIdx.x, tid = threadIdx.x, lane = tid & 31, wid = tid >> 5;
    int i = b * 1024 + tid;
    int v = (i < NN) ? g_deg[i] : 0;
    int x = v;
    #pragma unroll
    for (int o = 1; o < 32; o <<= 1) { int t = __shfl_up_sync(FULLMASK, x, o); if (lane >= o) x += t; }
    if (lane == 31) ws[wid] = x;
    __syncthreads();
    if (wid == 0) {
        int w = ws[lane];
        #pragma unroll
        for (int o = 1; o < 32; o <<= 1) { int t = __shfl_up_sync(FULLMASK, w, o); if (lane >= o) w += t; }
        ws[lane] = w;
    }
    __syncthreads();
    int incl = x + (wid ? ws[wid - 1] : 0);
    if (i < NN) g_rowptr[i + 1] = incl;     // block-local inclusive
    if (tid == 1023) g_bsum[b] = incl;
}

__global__ void scan_sums() {   // 1 block, 32 threads
    int lane = threadIdx.x;
    int run = 0;
    for (int base = 0; base < NB_SCAN; base += 32) {
        int idx = base + lane;
        int v = (idx < NB_SCAN) ? g_bsum[idx] : 0;
        int x = v;
        #pragma unroll
        for (int o = 1; o < 32; o <<= 1) { int t = __shfl_up_sync(FULLMASK, x, o); if (lane >= o) x += t; }
        if (idx < NB_SCAN) g_boff[idx] = run + x - v;   // exclusive
        run += __shfl_sync(FULLMASK, x, 31);
    }
}

__global__ void scan_apply() {
    int i = blockIdx.x * blockDim.x + threadIdx.x;
    if (i == 0) g_rowptr[0] = 0;
    if (i < NN) {
        int r = g_rowptr[i + 1] + g_boff[i >> 10];
        g_rowptr[i + 1] = r;
        g_cursor[i] = r - g_deg[i];
    }
}

__global__ void fill_kernel(const int* __restrict__ ei) {
    int i = blockIdx.x * blockDim.x + threadIdx.x;
    if (i >= ETOT) return;
    int src, dst;
    if (i < EE) { src = ei[i]; dst = ei[EE + i]; }
    else        { src = i - EE; dst = i - EE; }
    int pos = atomicAdd(&g_cursor[dst], 1);
    g_srcs[pos] = src;
}

// ---------------- TF32 tensor-core GEMM 1: g_h1 = x @ W1 ---------------------
// A [NN x 128] fp32 (guarded), B [128 x 256], C [NPAD x 256]. BM=128 BN=128 BK=32.
__global__ void gemm1_tc(const float* __restrict__ A, const float* __restrict__ B) {
    constexpr int LDA = 36, LDB = 136;
    __shared__ float As[128 * LDA];
    __shared__ float Bs[32 * LDB];
    int tid = threadIdx.x;
    int warp = tid >> 5;
    int wm = warp & 3;          // 0..3 -> rows wm*32
    int wn = warp >> 2;         // 0..1 -> cols wn*64
    int row0 = blockIdx.y * 128;
    int col0 = blockIdx.x * 128;

    wmma::fragment<wmma::accumulator, 16, 16, 8, float> c[2][4];
    #pragma unroll
    for (int i = 0; i < 2; i++)
        #pragma unroll
        for (int j = 0; j < 4; j++) wmma::fill_fragment(c[i][j], 0.0f);

    for (int k0 = 0; k0 < FIN; k0 += 32) {
        // A tile 128x32: 1024 float4, 4 per thread
        #pragma unroll
        for (int it = 0; it < 4; it++) {
            int idx = tid + it * 256;
            int r = idx >> 3, c4 = idx & 7;
            float4 v = make_float4(0.f, 0.f, 0.f, 0.f);
            if (row0 + r < NN)
                v = *reinterpret_cast<const float4*>(A + (size_t)(row0 + r) * FIN + k0 + c4 * 4);
            float* p = &As[r * LDA + c4 * 4];
            p[0] = wmma::__float_to_tf32(v.x); p[1] = wmma::__float_to_tf32(v.y);
            p[2] = wmma::__float_to_tf32(v.z); p[3] = wmma::__float_to_tf32(v.w);
        }
        // B tile 32x128: 1024 float4, 4 per thread
        #pragma unroll
        for (int it = 0; it < 4; it++) {
            int idx = tid + it * 256;
            int r = idx >> 5, c4 = idx & 31;
            float4 v = *reinterpret_cast<const float4*>(B + (size_t)(k0 + r) * F1 + col0 + c4 * 4);
            float* p = &Bs[r * LDB + c4 * 4];
            p[0] = wmma::__float_to_tf32(v.x); p[1] = wmma::__float_to_tf32(v.y);
            p[2] = wmma::__float_to_tf32(v.z); p[3] = wmma::__float_to_tf32(v.w);
        }
        __syncthreads();
        #pragma unroll
        for (int ks = 0; ks < 4; ks++) {
            wmma::fragment<wmma::matrix_a, 16, 16, 8, wmma::precision::tf32, wmma::row_major> a[2];
            wmma::fragment<wmma::matrix_b, 16, 16, 8, wmma::precision::tf32, wmma::row_major> b[4];
            #pragma unroll
            for (int i = 0; i < 2; i++)
                wmma::load_matrix_sync(a[i], &As[(wm * 32 + i * 16) * LDA + ks * 8], LDA);
            #pragma unroll
            for (int j = 0; j < 4; j++)
                wmma::load_matrix_sync(b[j], &Bs[(ks * 8) * LDB + wn * 64 + j * 16], LDB);
            #pragma unroll
            for (int i = 0; i < 2; i++)
                #pragma unroll
                for (int j = 0; j < 4; j++)
                    wmma::mma_sync(c[i][j], a[i], b[j], c[i][j]);
        }
        __syncthreads();
    }
    #pragma unroll
    for (int i = 0; i < 2; i++)
        #pragma unroll
        for (int j = 0; j < 4; j++)
            wmma::store_matrix_sync(
                &g_h1[(size_t)(row0 + wm * 32 + i * 16) * F1 + col0 + wn * 64 + j * 16],
                c[i][j], F1, wmma::mem_row_major);
}

// ---------------- TF32 tensor-core GEMM 2: g_h2 = g_out1 @ W2 ----------------
// A [NPAD x 256] (padding rows are zero), B [256 x 32], C [NPAD x 32]. BM=128 BN=32 BK=64.
__global__ void gemm2_tc(const float* __restrict__ B) {
    constexpr int LDA = 68, LDB = 36;
    __shared__ float As[128 * LDA];
    __shared__ float Bs[64 * LDB];
    int tid = threadIdx.x;     // 128 threads, 4 warps
    int warp = tid >> 5;       // row group warp*32
    int row0 = blockIdx.y * 128;

    wmma::fragment<wmma::accumulator, 16, 16, 8, float> c[2][2];
    #pragma unroll
    for (int i = 0; i < 2; i++)
        #pragma unroll
        for (int j = 0; j < 2; j++) wmma::fill_fragment(c[i][j], 0.0f);

    for (int k0 = 0; k0 < F1; k0 += 64) {
        // A tile 128x64: 2048 float4, 16 per thread
        #pragma unroll
        for (int it = 0; it < 16; it++) {
            int idx = tid + it * 128;
            int r = idx >> 4, c4 = idx & 15;
            float4 v = *reinterpret_cast<const float4*>(g_out1 + (size_t)(row0 + r) * F1 + k0 + c4 * 4);
            float* p = &As[r * LDA + c4 * 4];
            p[0] = wmma::__float_to_tf32(v.x); p[1] = wmma::__float_to_tf32(v.y);
            p[2] = wmma::__float_to_tf32(v.z); p[3] = wmma::__float_to_tf32(v.w);
        }
        // B tile 64x32: 512 float4, 4 per thread
        #pragma unroll
        for (int it = 0; it < 4; it++) {
            int idx = tid + it * 128;
            int r = idx >> 3, c4 = idx & 7;
            float4 v = *reinterpret_cast<const float4*>(B + (size_t)(k0 + r) * HIDC + c4 * 4);
            float* p = &Bs[r * LDB + c4 * 4];
            p[0] = wmma::__float_to_tf32(v.x); p[1] = wmma::__float_to_tf32(v.y);
            p[2] = wmma::__float_to_tf32(v.z); p[3] = wmma::__float_to_tf32(v.w);
        }
        __syncthreads();
        #pragma unroll
        for (int ks = 0; ks < 8; ks++) {
            wmma::fragment<wmma::matrix_a, 16, 16, 8, wmma::precision::tf32, wmma::row_major> a[2];
            wmma::fragment<wmma::matrix_b, 16, 16, 8, wmma::precision::tf32, wmma::row_major> b[2];
            #pragma unroll
            for (int i = 0; i < 2; i++)
                wmma::load_matrix_sync(a[i], &As[(warp * 32 + i * 16) * LDA + ks * 8], LDA);
            #pragma unroll
            for (int j = 0; j < 2; j++)
                wmma::load_matrix_sync(b[j], &Bs[(ks * 8) * LDB + j * 16], LDB);
            #pragma unroll
            for (int i = 0; i < 2; i++)
                #pragma unroll
                for (int j = 0; j < 2; j++)
                    wmma::mma_sync(c[i][j], a[i], b[j], c[i][j]);
        }
        __syncthreads();
    }
    #pragma unroll
    for (int i = 0; i < 2; i++)
        #pragma unroll
        for (int j = 0; j < 2; j++)
            wmma::store_matrix_sync(
                &g_h2[(size_t)(row0 + warp * 32 + i * 16) * HIDC + j * 16],
                c[i][j], HIDC, wmma::mem_row_major);
}

// ---------------- attention logit projections (+fp16 shadow for layer 1) -----
template <int LAYER>
__global__ void al_kernel(const float* __restrict__ asrc, const float* __restrict__ adst) {
    constexpr int H = (LAYER == 1) ? HEADS : 1;
    const float* hf = (LAYER == 1) ? g_h1 : g_h2;
    float* als = (LAYER == 1) ? g_als1 : g_als2;
    float* ald = (LAYER == 1) ? g_ald1 : g_ald2;
    int w = (blockIdx.x * blockDim.x + threadIdx.x) >> 5;
    int lane = threadIdx.x & 31;
    if (w >= NN) return;
    #pragma unroll
    for (int h = 0; h < H; h++) {
        float v = hf[(size_t)w * (H * HIDC) + h * HIDC + lane];
        if (LAYER == 1) g_h1h[(size_t)w * F1 + h * HIDC + lane] = __float2half(v);
        float ps = v * asrc[h * HIDC + lane];
        float pd = v * adst[h * HIDC + lane];
        #pragma unroll
        for (int off = 16; off; off >>= 1) {
            ps += __shfl_down_sync(FULLMASK, ps, off);
            pd += __shfl_down_sync(FULLMASK, pd, off);
        }
        if (lane == 0) { als[w * H + h] = ps; ald[w * H + h] = pd; }
    }
}

// ---------------- GAT layer 1: warp/node, smem alphas, fp16 gather -----------
__global__ void atten1_kernel(const float* __restrict__ bias) {
    __shared__ float s_alpha[8][32][9];   // [warp][edge-in-chunk][head] padded
    int node = (blockIdx.x * blockDim.x + threadIdx.x) >> 5;
    int lane = threadIdx.x & 31;
    int warp = (threadIdx.x >> 5) & 7;
    if (node >= NN) return;
    int start = g_rowptr[node], end = g_rowptr[node + 1];

    float ad[8];
    #pragma unroll
    for (int h = 0; h < 8; h++) ad[h] = g_ald1[node * 8 + h];

    // phase 1: online softmax stats, edges strided across lanes
    float m[8], z[8];
    #pragma unroll
    for (int h = 0; h < 8; h++) { m[h] = -INFINITY; z[h] = 0.0f; }
    for (int i = start + lane; i < end; i += 32) {
        int s = g_srcs[i];
        float4 a0 = *reinterpret_cast<const float4*>(g_als1 + (size_t)s * 8);
        float4 a1 = *reinterpret_cast<const float4*>(g_als1 + (size_t)s * 8 + 4);
        float av[8] = {a0.x, a0.y, a0.z, a0.w, a1.x, a1.y, a1.z, a1.w};
        #pragma unroll
        for (int h = 0; h < 8; h++) {
            float e = av[h] + ad[h];
            e = (e > 0.0f) ? e : 0.2f * e;
            float mn = fmaxf(m[h], e);
            z[h] = z[h] * __expf(m[h] - mn) + __expf(e - mn);
            m[h] = mn;
        }
    }
    #pragma unroll
    for (int off = 16; off; off >>= 1) {
        #pragma unroll
        for (int h = 0; h < 8; h++) {
            float mo = __shfl_down_sync(FULLMASK, m[h], off);
            float zo = __shfl_down_sync(FULLMASK, z[h], off);
            float mn = fmaxf(m[h], mo);
            float za = (m[h] != -INFINITY) ? z[h] * __expf(m[h] - mn) : 0.0f;
            float zb = (mo   != -INFINITY) ? zo   * __expf(mo   - mn) : 0.0f;
            m[h] = mn; z[h] = za + zb;
        }
    }
    float invz[8];
    #pragma unroll
    for (int h = 0; h < 8; h++) {
        m[h] = __shfl_sync(FULLMASK, m[h], 0);
        invz[h] = 1.0f / __shfl_sync(FULLMASK, z[h], 0);
    }

    // phase 2: chunked gather. lane owns half2 column pair; 2 heads per p.
    int hsel = lane >> 4;
    float2 acc[4];
    #pragma unroll
    for (int p = 0; p < 4; p++) acc[p] = make_float2(0.f, 0.f);
    const __half2* hbase = reinterpret_cast<const __half2*>(g_h1h);

    for (int i = start; i < end; i += 32) {
        int cnt = min(32, end - i);
        int sreg = (lane < cnt) ? g_srcs[i + lane] : 0;
        if (lane < cnt) {
            float4 a0 = *reinterpret_cast<const float4*>(g_als1 + (size_t)sreg * 8);
            float4 a1 = *reinterpret_cast<const float4*>(g_als1 + (size_t)sreg * 8 + 4);
            float av[8] = {a0.x, a0.y, a0.z, a0.w, a1.x, a1.y, a1.z, a1.w};
            #pragma unroll
            for (int h = 0; h < 8; h++) {
                float e = av[h] + ad[h];
                e = (e > 0.0f) ? e : 0.2f * e;
                s_alpha[warp][lane][h] = __expf(e - m[h]) * invz[h];
            }
        }
        __syncwarp();
        if (cnt == 32) {
            #pragma unroll 4
            for (int j = 0; j < 32; j++) {
                int s = __shfl_sync(FULLMASK, sreg, j);
                const __half2* hv = hbase + (size_t)s * 128 + lane;
                #pragma unroll
                for (int p = 0; p < 4; p++) {
                    float alpha = s_alpha[warp][j][2 * p + hsel];
                    float2 f = __half22float2(hv[p * 32]);
                    acc[p].x += alpha * f.x;
                    acc[p].y += alpha * f.y;
                }
            }
        } else {
            for (int j = 0; j < cnt; j++) {
                int s = __shfl_sync(FULLMASK, sreg, j);
                const __half2* hv = hbase + (size_t)s * 128 + lane;
                #pragma unroll
                for (int p = 0; p < 4; p++) {
                    float alpha = s_alpha[warp][j][2 * p + hsel];
                    float2 f = __half22float2(hv[p * 32]);
                    acc[p].x += alpha * f.x;
                    acc[p].y += alpha * f.y;
                }
            }
        }
        __syncwarp();
    }
    #pragma unroll
    for (int p = 0; p < 4; p++) {
        int c = p * 64 + 2 * lane;
        float vx = fmaxf(acc[p].x + bias[c], 0.0f);
        float vy = fmaxf(acc[p].y + bias[c + 1], 0.0f);
        *reinterpret_cast<float2*>(&g_out1[(size_t)node * F1 + c]) = make_float2(vx, vy);
    }
}

// ---------------- GAT layer 2 (H=1, fp32 gather) -----------------------------
__global__ void atten2_kernel(const float* __restrict__ bias) {
    __shared__ float s_alpha[8][32];
    int node = (blockIdx.x * blockDim.x + threadIdx.x) >> 5;
    int lane = threadIdx.x & 31;
    int warp = (threadIdx.x >> 5) & 7;
    if (node >= NN) return;
    int start = g_rowptr[node], end = g_rowptr[node + 1];
    float ad = g_ald2[node];

    float m = -INFINITY, z = 0.0f;
    for (int i = start + lane; i < end; i += 32) {
        float e = g_als2[g_srcs[i]] + ad;
        e = (e > 0.0f) ? e : 0.2f * e;
        float mn = fmaxf(m, e);
        z = z * __expf(m - mn) + __expf(e - mn);
        m = mn;
    }
    #pragma unroll
    for (int off = 16; off; off >>= 1) {
        float mo = __shfl_down_sync(FULLMASK, m, off);
        float zo = __shfl_down_sync(FULLMASK, z, off);
        float mn = fmaxf(m, mo);
        float za = (m  != -INFINITY) ? z  * __expf(m  - mn) : 0.0f;
        float zb = (mo != -INFINITY) ? zo * __expf(mo - mn) : 0.0f;
        m = mn; z = za + zb;
    }
    m = __shfl_sync(FULLMASK, m, 0);
    float invz = 1.0f / __shfl_sync(FULLMASK, z, 0);

    float acc = 0.0f;
    for (int i = start; i < end; i += 32) {
        int cnt = min(32, end - i);
        int sreg = (lane < cnt) ? g_srcs[i + lane] : 0;
        if (lane < cnt) {
            float e = g_als2[sreg] + ad;
            e = (e > 0.0f) ? e : 0.2f * e;
            s_alpha[warp][lane] = __expf(e - m) * invz;
        }
        __syncwarp();
        for (int j = 0; j < cnt; j++) {
            int s = __shfl_sync(FULLMASK, sreg, j);
            acc += s_alpha[warp][j] * g_h2[(size_t)s * HIDC + lane];
        }
        __syncwarp();
    }
    g_out2[(size_t)node * HIDC + lane] = acc + bias[lane];
}

// ---------------- pooling ----------------------------------------------------
__global__ void pool_kernel(const int* __restrict__ batch) {
    int w = (blockIdx.x * blockDim.x + threadIdx.x) >> 5;
    int lane = threadIdx.x & 31;
    if (w >= NN) return;
    int g = batch[w];
    atomicAdd(&g_sums[g * HIDC + lane], g_out2[(size_t)w * HIDC + lane]);
    if (lane == 0) atomicAdd(&g_cnts[g], 1);
}

__global__ void div_kernel(float* __restrict__ out) {
    int i = blockIdx.x * blockDim.x + threadIdx.x;
    if (i < NG * HIDC)
        out[i] = g_sums[i] / fmaxf((float)g_cnts[i / HIDC], 1.0f);
}

// ---------------- launch -----------------------------------------------------
extern "C" void kernel_launch(void* const* d_in, const int* in_sizes, int n_in,
                              void* d_out, int out_size) {
    const float* x   = (const float*)d_in[0];
    const int*   ei  = (const int*)d_in[1];
    // d_in[2] edge_attr: unused by reference (lin_edge=None)
    const int* batch = (const int*)d_in[3];
    const float* W1  = (const float*)d_in[4];
    const float* as1 = (const float*)d_in[5];
    const float* ad1 = (const float*)d_in[6];
    const float* b1  = (const float*)d_in[7];
    const float* W2  = (const float*)d_in[8];
    const float* as2 = (const float*)d_in[9];
    const float* ad2 = (const float*)d_in[10];
    const float* b2  = (const float*)d_in[11];
    float* out = (float*)d_out;

    const int WB = (NN * 32 + 255) / 256;   // warp-per-node grids (6250)
    const int MB = (NN + 127) / 128;        // 391

    zero_kernel<<<(NN + 255) / 256, 256>>>();
    deg_kernel<<<(ETOT + 255) / 256, 256>>>(ei);
    scan_blocks<<<NB_SCAN, 1024>>>();
    scan_sums<<<1, 32>>>();
    scan_apply<<<(NN + 255) / 256, 256>>>();
    fill_kernel<<<(ETOT + 255) / 256, 256>>>(ei);

    gemm1_tc<<<dim3(2, MB), 256>>>(x, W1);
    al_kernel<1><<<WB, 256>>>(as1, ad1);
    atten1_kernel<<<WB, 256>>>(b1);

    gemm2_tc<<<dim3(1, MB), 128>>>(W2);
    al_kernel<2><<<WB, 256>>>(as2, ad2);
    atten2_kernel<<<WB, 256>>>(b2);

    pool_kernel<<<WB, 256>>>(batch);
    div_kernel<<<(NG * HIDC + 255) / 256, 256>>>(out);
}

// round 6
// speedup vs baseline: 2.9221x; 1.3669x over previous
#include <cuda_runtime.h>
#include <cuda_fp16.h>
#include <mma.h>
#include <math.h>

using namespace nvcuda;

#define NN 50000
#define NPAD 50048         // 391 * 128, wmma padded
#define EE 800000
#define ETOT 850000        // EE + NN self loops
#define FIN 128
#define HIDC 32
#define HEADS 8
#define NG 64
#define F1 256             // HEADS*HIDC
#define FULLMASK 0xffffffffu
#define NB_SCAN ((NN + 1023) / 1024)   // 49

// ---------------- scratch (static device memory; no allocs allowed) ----------
__device__ __half g_h1h[(size_t)NN * F1];      // x @ W1, fp16      [N,256]
__device__ __half g_out1h[(size_t)NPAD * F1];  // relu(gat1)+b1     [Npad,256] (pad rows stay 0)
__device__ float  g_h2[(size_t)NPAD * HIDC];   // out1 @ W2         [Npad,32]
__device__ float  g_als1[NN * HEADS];
__device__ float  g_ald1[NN * HEADS];
__device__ float  g_als2[NN];
__device__ float  g_ald2[NN];
__device__ int    g_deg[NN];
__device__ int    g_rowptr[NN + 1];
__device__ int    g_cursor[NN];
__device__ int    g_srcs[ETOT];
__device__ int    g_bsum[NB_SCAN];
__device__ int    g_boff[NB_SCAN];
__device__ float  g_sums[NG * HIDC];
__device__ int    g_cnts[NG];

// ---------------- small utility kernels --------------------------------------
__global__ void zero_kernel() {
    int i = blockIdx.x * blockDim.x + threadIdx.x;
    if (i < NN) g_deg[i] = 0;
    if (i < NG * HIDC) g_sums[i] = 0.0f;
    if (i < NG) g_cnts[i] = 0;
}

__global__ void deg_kernel(const int* __restrict__ ei) {
    int i = blockIdx.x * blockDim.x + threadIdx.x;
    if (i >= ETOT) return;
    int dst = (i < EE) ? ei[EE + i] : (i - EE);
    atomicAdd(&g_deg[dst], 1);
}

__global__ void cnt_kernel(const int* __restrict__ batch) {
    __shared__ int hist[NG];
    int tid = threadIdx.x;
    if (tid < NG) hist[tid] = 0;
    __syncthreads();
    int i = blockIdx.x * blockDim.x + tid;
    if (i < NN) atomicAdd(&hist[batch[i]], 1);
    __syncthreads();
    if (tid < NG && hist[tid]) atomicAdd(&g_cnts[tid], hist[tid]);
}

// ---- 3-kernel scan ----------------------------------------------------------
__global__ void scan_blocks() {
    __shared__ int ws[32];
    int b = blockIdx.x, tid = threadIdx.x, lane = tid & 31, wid = tid >> 5;
    int i = b * 1024 + tid;
    int v = (i < NN) ? g_deg[i] : 0;
    int x = v;
    #pragma unroll
    for (int o = 1; o < 32; o <<= 1) { int t = __shfl_up_sync(FULLMASK, x, o); if (lane >= o) x += t; }
    if (lane == 31) ws[wid] = x;
    __syncthreads();
    if (wid == 0) {
        int w = ws[lane];
        #pragma unroll
        for (int o = 1; o < 32; o <<= 1) { int t = __shfl_up_sync(FULLMASK, w, o); if (lane >= o) w += t; }
        ws[lane] = w;
    }
    __syncthreads();
    int incl = x + (wid ? ws[wid - 1] : 0);
    if (i < NN) g_rowptr[i + 1] = incl;
    if (tid == 1023) g_bsum[b] = incl;
}

__global__ void scan_sums() {
    int lane = threadIdx.x;
    int run = 0;
    for (int base = 0; base < NB_SCAN; base += 32) {
        int idx = base + lane;
        int v = (idx < NB_SCAN) ? g_bsum[idx] : 0;
        int x = v;
        #pragma unroll
        for (int o = 1; o < 32; o <<= 1) { int t = __shfl_up_sync(FULLMASK, x, o); if (lane >= o) x += t; }
        if (idx < NB_SCAN) g_boff[idx] = run + x - v;
        run += __shfl_sync(FULLMASK, x, 31);
    }
}

__global__ void scan_apply() {
    int i = blockIdx.x * blockDim.x + threadIdx.x;
    if (i == 0) g_rowptr[0] = 0;
    if (i < NN) {
        int r = g_rowptr[i + 1] + g_boff[i >> 10];
        g_rowptr[i + 1] = r;
        g_cursor[i] = r - g_deg[i];
    }
}

__global__ void fill_kernel(const int* __restrict__ ei) {
    int i = blockIdx.x * blockDim.x + threadIdx.x;
    if (i >= ETOT) return;
    int src, dst;
    if (i < EE) { src = ei[i]; dst = ei[EE + i]; }
    else        { src = i - EE; dst = i - EE; }
    int pos = atomicAdd(&g_cursor[dst], 1);
    g_srcs[pos] = src;
}

// ---------------- TF32 GEMM 1: g_h1h(fp16) = x @ W1 --------------------------
__global__ void gemm1_tc(const float* __restrict__ A, const float* __restrict__ B) {
    constexpr int LDA = 36, LDB = 136, LDS = 20;   // LDS: multiple of 4 floats (16B)
    __shared__ float As[128 * LDA];
    __shared__ float Bs[32 * LDB];
    __shared__ float scr[8][16 * LDS];
    int tid = threadIdx.x;
    int lane = tid & 31;
    int warp = tid >> 5;
    int wm = warp & 3;
    int wn = warp >> 2;
    int row0 = blockIdx.y * 128;
    int col0 = blockIdx.x * 128;

    wmma::fragment<wmma::accumulator, 16, 16, 8, float> c[2][4];
    #pragma unroll
    for (int i = 0; i < 2; i++)
        #pragma unroll
        for (int j = 0; j < 4; j++) wmma::fill_fragment(c[i][j], 0.0f);

    for (int k0 = 0; k0 < FIN; k0 += 32) {
        #pragma unroll
        for (int it = 0; it < 4; it++) {
            int idx = tid + it * 256;
            int r = idx >> 3, c4 = idx & 7;
            float4 v = make_float4(0.f, 0.f, 0.f, 0.f);
            if (row0 + r < NN)
                v = *reinterpret_cast<const float4*>(A + (size_t)(row0 + r) * FIN + k0 + c4 * 4);
            float* p = &As[r * LDA + c4 * 4];
            p[0] = wmma::__float_to_tf32(v.x); p[1] = wmma::__float_to_tf32(v.y);
            p[2] = wmma::__float_to_tf32(v.z); p[3] = wmma::__float_to_tf32(v.w);
        }
        #pragma unroll
        for (int it = 0; it < 4; it++) {
            int idx = tid + it * 256;
            int r = idx >> 5, c4 = idx & 31;
            float4 v = *reinterpret_cast<const float4*>(B + (size_t)(k0 + r) * F1 + col0 + c4 * 4);
            float* p = &Bs[r * LDB + c4 * 4];
            p[0] = wmma::__float_to_tf32(v.x); p[1] = wmma::__float_to_tf32(v.y);
            p[2] = wmma::__float_to_tf32(v.z); p[3] = wmma::__float_to_tf32(v.w);
        }
        __syncthreads();
        #pragma unroll
        for (int ks = 0; ks < 4; ks++) {
            wmma::fragment<wmma::matrix_a, 16, 16, 8, wmma::precision::tf32, wmma::row_major> a[2];
            wmma::fragment<wmma::matrix_b, 16, 16, 8, wmma::precision::tf32, wmma::row_major> b[4];
            #pragma unroll
            for (int i = 0; i < 2; i++)
                wmma::load_matrix_sync(a[i], &As[(wm * 32 + i * 16) * LDA + ks * 8], LDA);
            #pragma unroll
            for (int j = 0; j < 4; j++)
                wmma::load_matrix_sync(b[j], &Bs[(ks * 8) * LDB + wn * 64 + j * 16], LDB);
            #pragma unroll
            for (int i = 0; i < 2; i++)
                #pragma unroll
                for (int j = 0; j < 4; j++)
                    wmma::mma_sync(c[i][j], a[i], b[j], c[i][j]);
        }
        __syncthreads();
    }
    // epilogue: fragments -> smem (legal ldm) -> fp16 global
    #pragma unroll
    for (int i = 0; i < 2; i++)
        #pragma unroll
        for (int j = 0; j < 4; j++) {
            wmma::store_matrix_sync(&scr[warp][0], c[i][j], LDS, wmma::mem_row_major);
            __syncwarp();
            int r = row0 + wm * 32 + i * 16 + (lane >> 1);
            int cc = col0 + wn * 64 + j * 16 + (lane & 1) * 8;
            if (r < NN) {
                const float* sp = &scr[warp][(lane >> 1) * LDS + (lane & 1) * 8];
                __half2 h4[4];
                #pragma unroll
                for (int q = 0; q < 4; q++)
                    h4[q] = __floats2half2_rn(sp[2 * q], sp[2 * q + 1]);
                *reinterpret_cast<uint4*>(&g_h1h[(size_t)r * F1 + cc]) =
                    *reinterpret_cast<uint4*>(h4);
            }
            __syncwarp();
        }
}

// ---------------- TF32 GEMM 2: g_h2 = out1h(fp16) @ W2 -----------------------
__global__ void gemm2_tc(const float* __restrict__ B) {
    constexpr int LDA = 68, LDB = 36;
    __shared__ float As[128 * LDA];
    __shared__ float Bs[64 * LDB];
    int tid = threadIdx.x;     // 128 threads, 4 warps
    int warp = tid >> 5;
    int row0 = blockIdx.y * 128;

    wmma::fragment<wmma::accumulator, 16, 16, 8, float> c[2][2];
    #pragma unroll
    for (int i = 0; i < 2; i++)
        #pragma unroll
        for (int j = 0; j < 2; j++) wmma::fill_fragment(c[i][j], 0.0f);

    for (int k0 = 0; k0 < F1; k0 += 64) {
        // A tile 128x64 fp16: 1024 uint4 (8 halfs each), 8 per thread
        #pragma unroll
        for (int it = 0; it < 8; it++) {
            int idx = tid + it * 128;
            int r = idx >> 3, c8 = idx & 7;
            uint4 raw = *reinterpret_cast<const uint4*>(
                &g_out1h[(size_t)(row0 + r) * F1 + k0 + c8 * 8]);
            __half2* h2 = reinterpret_cast<__half2*>(&raw);
            float* p = &As[r * LDA + c8 * 8];
            #pragma unroll
            for (int q = 0; q < 4; q++) {
                float2 f = __half22float2(h2[q]);
                p[2 * q]     = wmma::__float_to_tf32(f.x);
                p[2 * q + 1] = wmma::__float_to_tf32(f.y);
            }
        }
        #pragma unroll
        for (int it = 0; it < 4; it++) {
            int idx = tid + it * 128;
            int r = idx >> 3, c4 = idx & 7;
            float4 v = *reinterpret_cast<const float4*>(B + (size_t)(k0 + r) * HIDC + c4 * 4);
            float* p = &Bs[r * LDB + c4 * 4];
            p[0] = wmma::__float_to_tf32(v.x); p[1] = wmma::__float_to_tf32(v.y);
            p[2] = wmma::__float_to_tf32(v.z); p[3] = wmma::__float_to_tf32(v.w);
        }
        __syncthreads();
        #pragma unroll
        for (int ks = 0; ks < 8; ks++) {
            wmma::fragment<wmma::matrix_a, 16, 16, 8, wmma::precision::tf32, wmma::row_major> a[2];
            wmma::fragment<wmma::matrix_b, 16, 16, 8, wmma::precision::tf32, wmma::row_major> b[2];
            #pragma unroll
            for (int i = 0; i < 2; i++)
                wmma::load_matrix_sync(a[i], &As[(warp * 32 + i * 16) * LDA + ks * 8], LDA);
            #pragma unroll
            for (int j = 0; j < 2; j++)
                wmma::load_matrix_sync(b[j], &Bs[(ks * 8) * LDB + j * 16], LDB);
            #pragma unroll
            for (int i = 0; i < 2; i++)
                #pragma unroll
                for (int j = 0; j < 2; j++)
                    wmma::mma_sync(c[i][j], a[i], b[j], c[i][j]);
        }
        __syncthreads();
    }
    #pragma unroll
    for (int i = 0; i < 2; i++)
        #pragma unroll
        for (int j = 0; j < 2; j++)
            wmma::store_matrix_sync(
                &g_h2[(size_t)(row0 + warp * 32 + i * 16) * HIDC + j * 16],
                c[i][j], HIDC, wmma::mem_row_major);
}

// ---------------- attention logit projections --------------------------------
// layer 1: reads fp16 h1h, 2 heads per pass (16-lane segmented reduce)
__global__ void al1_kernel(const float* __restrict__ asrc, const float* __restrict__ adst) {
    int w = (blockIdx.x * blockDim.x + threadIdx.x) >> 5;
    int lane = threadIdx.x & 31;
    if (w >= NN) return;
    const __half2* hh = reinterpret_cast<const __half2*>(g_h1h) + (size_t)w * 128;
    #pragma unroll
    for (int hp = 0; hp < 4; hp++) {
        float2 f = __half22float2(hh[hp * 32 + lane]);
        int h = hp * 2 + (lane >> 4);
        int c = (lane & 15) * 2;
        float ps = f.x * asrc[h * HIDC + c] + f.y * asrc[h * HIDC + c + 1];
        float pd = f.x * adst[h * HIDC + c] + f.y * adst[h * HIDC + c + 1];
        #pragma unroll
        for (int off = 8; off; off >>= 1) {
            ps += __shfl_down_sync(FULLMASK, ps, off, 16);
            pd += __shfl_down_sync(FULLMASK, pd, off, 16);
        }
        if ((lane & 15) == 0) { g_als1[w * HEADS + h] = ps; g_ald1[w * HEADS + h] = pd; }
    }
}

__global__ void al2_kernel(const float* __restrict__ asrc, const float* __restrict__ adst) {
    int w = (blockIdx.x * blockDim.x + threadIdx.x) >> 5;
    int lane = threadIdx.x & 31;
    if (w >= NN) return;
    float v = g_h2[(size_t)w * HIDC + lane];
    float ps = v * asrc[lane];
    float pd = v * adst[lane];
    #pragma unroll
    for (int off = 16; off; off >>= 1) {
        ps += __shfl_down_sync(FULLMASK, ps, off);
        pd += __shfl_down_sync(FULLMASK, pd, off);
    }
    if (lane == 0) { g_als2[w] = ps; g_ald2[w] = pd; }
}

// ---------------- GAT layer 1: single-pass (no max-shift), fp16 gather -------
__global__ void atten1_kernel(const float* __restrict__ bias) {
    __shared__ float s_w[8][32][9];   // [warp][edge-in-chunk][head] padded
    int node = (blockIdx.x * blockDim.x + threadIdx.x) >> 5;
    int lane = threadIdx.x & 31;
    int warp = (threadIdx.x >> 5) & 7;
    if (node >= NN) return;
    int start = g_rowptr[node], end = g_rowptr[node + 1];

    float ad[8];
    #pragma unroll
    for (int h = 0; h < 8; h++) ad[h] = g_ald1[node * 8 + h];

    int hsel = lane >> 4;
    float2 acc[4];
    #pragma unroll
    for (int p = 0; p < 4; p++) acc[p] = make_float2(0.f, 0.f);
    float z[8];
    #pragma unroll
    for (int h = 0; h < 8; h++) z[h] = 0.0f;
    const __half2* hbase = reinterpret_cast<const __half2*>(g_h1h);

    for (int i = start; i < end; i += 32) {
        int cnt = min(32, end - i);
        int sreg = (lane < cnt) ? g_srcs[i + lane] : 0;
        if (lane < cnt) {
            float4 a0 = *reinterpret_cast<const float4*>(g_als1 + (size_t)sreg * 8);
            float4 a1 = *reinterpret_cast<const float4*>(g_als1 + (size_t)sreg * 8 + 4);
            float av[8] = {a0.x, a0.y, a0.z, a0.w, a1.x, a1.y, a1.z, a1.w};
            #pragma unroll
            for (int h = 0; h < 8; h++) {
                float e = av[h] + ad[h];
                e = (e > 0.0f) ? e : 0.2f * e;
                float wv = __expf(e);
                s_w[warp][lane][h] = wv;
                z[h] += wv;
            }
        }
        __syncwarp();
        if (cnt == 32) {
            #pragma unroll 4
            for (int j = 0; j < 32; j++) {
                int s = __shfl_sync(FULLMASK, sreg, j);
                const __half2* hv = hbase + (size_t)s * 128 + lane;
                #pragma unroll
                for (int p = 0; p < 4; p++) {
                    float wv = s_w[warp][j][2 * p + hsel];
                    float2 f = __half22float2(hv[p * 32]);
                    acc[p].x += wv * f.x;
                    acc[p].y += wv * f.y;
                }
            }
        } else {
            for (int j = 0; j < cnt; j++) {
                int s = __shfl_sync(FULLMASK, sreg, j);
                const __half2* hv = hbase + (size_t)s * 128 + lane;
                #pragma unroll
                for (int p = 0; p < 4; p++) {
                    float wv = s_w[warp][j][2 * p + hsel];
                    float2 f = __half22float2(hv[p * 32]);
                    acc[p].x += wv * f.x;
                    acc[p].y += wv * f.y;
                }
            }
        }
        __syncwarp();
    }
    // reduce z across lanes, broadcast
    float invz[8];
    #pragma unroll
    for (int h = 0; h < 8; h++) {
        float zz = z[h];
        #pragma unroll
        for (int off = 16; off; off >>= 1) zz += __shfl_down_sync(FULLMASK, zz, off);
        invz[h] = 1.0f / __shfl_sync(FULLMASK, zz, 0);
    }
    #pragma unroll
    for (int p = 0; p < 4; p++) {
        int c = p * 64 + 2 * lane;
        float iz = invz[2 * p + hsel];
        float vx = fmaxf(acc[p].x * iz + bias[c], 0.0f);
        float vy = fmaxf(acc[p].y * iz + bias[c + 1], 0.0f);
        reinterpret_cast<__half2*>(g_out1h)[(size_t)node * 128 + p * 32 + lane] =
            __floats2half2_rn(vx, vy);
    }
}

// ---------------- GAT layer 2 single-pass + fused mean-pool sums -------------
__global__ void atten2_kernel(const float* __restrict__ bias, const int* __restrict__ batch) {
    __shared__ float s_w[8][32];
    int node = (blockIdx.x * blockDim.x + threadIdx.x) >> 5;
    int lane = threadIdx.x & 31;
    int warp = (threadIdx.x >> 5) & 7;
    if (node >= NN) return;
    int start = g_rowptr[node], end = g_rowptr[node + 1];
    float ad = g_ald2[node];

    float acc = 0.0f, z = 0.0f;
    for (int i = start; i < end; i += 32) {
        int cnt = min(32, end - i);
        int sreg = (lane < cnt) ? g_srcs[i + lane] : 0;
        if (lane < cnt) {
            float e = g_als2[sreg] + ad;
            e = (e > 0.0f) ? e : 0.2f * e;
            float wv = __expf(e);
            s_w[warp][lane] = wv;
            z += wv;
        }
        __syncwarp();
        for (int j = 0; j < cnt; j++) {
            int s = __shfl_sync(FULLMASK, sreg, j);
            acc += s_w[warp][j] * g_h2[(size_t)s * HIDC + lane];
        }
        __syncwarp();
    }
    #pragma unroll
    for (int off = 16; off; off >>= 1) z += __shfl_down_sync(FULLMASK, z, off);
    float invz = 1.0f / __shfl_sync(FULLMASK, z, 0);

    float outv = acc * invz + bias[lane];
    atomicAdd(&g_sums[batch[node] * HIDC + lane], outv);
}

__global__ void div_kernel(float* __restrict__ out) {
    int i = blockIdx.x * blockDim.x + threadIdx.x;
    if (i < NG * HIDC)
        out[i] = g_sums[i] / fmaxf((float)g_cnts[i / HIDC], 1.0f);
}

// ---------------- launch -----------------------------------------------------
extern "C" void kernel_launch(void* const* d_in, const int* in_sizes, int n_in,
                              void* d_out, int out_size) {
    const float* x   = (const float*)d_in[0];
    const int*   ei  = (const int*)d_in[1];
    // d_in[2] edge_attr: unused by reference (lin_edge=None)
    const int* batch = (const int*)d_in[3];
    const float* W1  = (const float*)d_in[4];
    const float* as1 = (const float*)d_in[5];
    const float* ad1 = (const float*)d_in[6];
    const float* b1  = (const float*)d_in[7];
    const float* W2  = (const float*)d_in[8];
    const float* as2 = (const float*)d_in[9];
    const float* ad2 = (const float*)d_in[10];
    const float* b2  = (const float*)d_in[11];
    float* out = (float*)d_out;

    const int WB = (NN * 32 + 255) / 256;   // warp-per-node grids (6250)
    const int MB = (NN + 127) / 128;        // 391

    zero_kernel<<<(NN + 255) / 256, 256>>>();
    deg_kernel<<<(ETOT + 255) / 256, 256>>>(ei);
    cnt_kernel<<<(NN + 255) / 256, 256>>>(batch);
    scan_blocks<<<NB_SCAN, 1024>>>();
    scan_sums<<<1, 32>>>();
    scan_apply<<<(NN + 255) / 256, 256>>>();
    fill_kernel<<<(ETOT + 255) / 256, 256>>>(ei);

    gemm1_tc<<<dim3(2, MB), 256>>>(x, W1);
    al1_kernel<<<WB, 256>>>(as1, ad1);
    atten1_kernel<<<WB, 256>>>(b1);

    gemm2_tc<<<dim3(1, MB), 128>>>(W2);
    al2_kernel<<<WB, 256>>>(as2, ad2);
    atten2_kernel<<<WB, 256>>>(b2, batch);

    div_kernel<<<(NG * HIDC + 255) / 256, 256>>>(out);
}

// round 10
// speedup vs baseline: 3.0674x; 1.0497x over previous
#include <cuda_runtime.h>
#include <cuda_fp16.h>
#include <mma.h>
#include <math.h>

using namespace nvcuda;

#define NN 50000
#define NPAD 50048         // 391 * 128, wmma padded
#define EE 800000
#define ETOT 850000        // EE + NN self loops
#define FIN 128
#define HIDC 32
#define HEADS 8
#define NG 64
#define F1 256             // HEADS*HIDC
#define FULLMASK 0xffffffffu
#define NB_SCAN ((NN + 1023) / 1024)   // 49
#define EB 831             // edge blocks: EB*256*4 >= ETOT
#define ESTRIDE (EB * 256)

// ---------------- scratch (static device memory; no allocs allowed) ----------
__device__ __half g_h1h[(size_t)NN * F1];      // x @ W1, fp16      [N,256]
__device__ __half g_out1h[(size_t)NPAD * F1];  // relu(gat1)+b1     [Npad,256] (pad rows stay 0)
__device__ __half g_h2h[(size_t)NPAD * HIDC];  // out1 @ W2, fp16   [Npad,32]
__device__ __half g_w2h[F1 * HIDC];            // W2 in fp16
__device__ float  g_als1[NN * HEADS];
__device__ float  g_ald1[NN * HEADS];
__device__ float  g_als2[NN];
__device__ float  g_ald2[NN];
__device__ int    g_deg[NN];
__device__ int    g_rowptr[NN + 1];
__device__ int    g_cursor[NN];
__device__ int    g_srcs[ETOT];
__device__ int    g_bsum[NB_SCAN];
__device__ int    g_boff[NB_SCAN];
__device__ float  g_sums[NG * HIDC];
__device__ int    g_cnts[NG];

// ---------------- zero + W2 fp16 convert -------------------------------------
__global__ void zero_kernel(const float* __restrict__ W2) {
    int i = blockIdx.x * blockDim.x + threadIdx.x;   // covers NN*8 = 400000
    if (i < NN * HEADS) { g_als1[i] = 0.0f; g_ald1[i] = 0.0f; }
    if (i < NN) g_deg[i] = 0;
    if (i < F1 * HIDC) g_w2h[i] = __float2half(W2[i]);
    if (i < NG * HIDC) g_sums[i] = 0.0f;
    if (i < NG) g_cnts[i] = 0;
}

// degree histogram (4 strided edges / thread) + graph-size histogram
__global__ void deg_kernel(const int* __restrict__ ei, const int* __restrict__ batch) {
    __shared__ int hist[NG];
    int tid = threadIdx.x;
    if (tid < NG) hist[tid] = 0;
    __syncthreads();
    int t = blockIdx.x * blockDim.x + tid;
    #pragma unroll
    for (int u = 0; u < 4; u++) {
        int i = t + u * ESTRIDE;
        if (i < ETOT) {
            int dst = (i < EE) ? ei[EE + i] : (i - EE);
            atomicAdd(&g_deg[dst], 1);
        }
    }
    if (t < NN) atomicAdd(&hist[batch[t]], 1);
    __syncthreads();
    if (tid < NG && hist[tid]) atomicAdd(&g_cnts[tid], hist[tid]);
}

// ---- 3-kernel scan ----------------------------------------------------------
__global__ void scan_blocks() {
    __shared__ int ws[32];
    int b = blockIdx.x, tid = threadIdx.x, lane = tid & 31, wid = tid >> 5;
    int i = b * 1024 + tid;
    int v = (i < NN) ? g_deg[i] : 0;
    int x = v;
    #pragma unroll
    for (int o = 1; o < 32; o <<= 1) { int t = __shfl_up_sync(FULLMASK, x, o); if (lane >= o) x += t; }
    if (lane == 31) ws[wid] = x;
    __syncthreads();
    if (wid == 0) {
        int w = ws[lane];
        #pragma unroll
        for (int o = 1; o < 32; o <<= 1) { int t = __shfl_up_sync(FULLMASK, w, o); if (lane >= o) w += t; }
        ws[lane] = w;
    }
    __syncthreads();
    int incl = x + (wid ? ws[wid - 1] : 0);
    if (i < NN) g_rowptr[i + 1] = incl;
    if (tid == 1023) g_bsum[b] = incl;
}

__global__ void scan_sums() {
    int lane = threadIdx.x;
    int run = 0;
    for (int base = 0; base < NB_SCAN; base += 32) {
        int idx = base + lane;
        int v = (idx < NB_SCAN) ? g_bsum[idx] : 0;
        int x = v;
        #pragma unroll
        for (int o = 1; o < 32; o <<= 1) { int t = __shfl_up_sync(FULLMASK, x, o); if (lane >= o) x += t; }
        if (idx < NB_SCAN) g_boff[idx] = run + x - v;
        run += __shfl_sync(FULLMASK, x, 31);
    }
}

__global__ void scan_apply() {
    int i = blockIdx.x * blockDim.x + threadIdx.x;
    if (i == 0) g_rowptr[0] = 0;
    if (i < NN) {
        int r = g_rowptr[i + 1] + g_boff[i >> 10];
        g_rowptr[i + 1] = r;
        g_cursor[i] = r - g_deg[i];
    }
}

__global__ void fill_kernel(const int* __restrict__ ei) {
    int t = blockIdx.x * blockDim.x + threadIdx.x;
    #pragma unroll
    for (int u = 0; u < 4; u++) {
        int i = t + u * ESTRIDE;
        if (i < ETOT) {
            int src, dst;
            if (i < EE) { src = ei[i]; dst = ei[EE + i]; }
            else        { src = i - EE; dst = i - EE; }
            int pos = atomicAdd(&g_cursor[dst], 1);
            g_srcs[pos] = src;
        }
    }
}

// ---------------- TF32 GEMM 1: g_h1h(fp16) = x @ W1, fused al1 ---------------
__global__ void gemm1_tc(const float* __restrict__ A, const float* __restrict__ B,
                         const float* __restrict__ asrc, const float* __restrict__ adst) {
    constexpr int LDA = 36, LDB = 136, LDS = 20;   // LDS: multiple of 4 floats (16B)
    __shared__ float As[128 * LDA];
    __shared__ float Bs[32 * LDB];
    __shared__ float scr[8][16 * LDS];
    int tid = threadIdx.x;
    int lane = tid & 31;
    int warp = tid >> 5;
    int wm = warp & 3;
    int wn = warp >> 2;
    int row0 = blockIdx.y * 128;
    int col0 = blockIdx.x * 128;

    wmma::fragment<wmma::accumulator, 16, 16, 8, float> c[2][4];
    #pragma unroll
    for (int i = 0; i < 2; i++)
        #pragma unroll
        for (int j = 0; j < 4; j++) wmma::fill_fragment(c[i][j], 0.0f);

    for (int k0 = 0; k0 < FIN; k0 += 32) {
        #pragma unroll
        for (int it = 0; it < 4; it++) {
            int idx = tid + it * 256;
            int r = idx >> 3, c4 = idx & 7;
            float4 v = make_float4(0.f, 0.f, 0.f, 0.f);
            if (row0 + r < NN)
                v = *reinterpret_cast<const float4*>(A + (size_t)(row0 + r) * FIN + k0 + c4 * 4);
            float* p = &As[r * LDA + c4 * 4];
            p[0] = wmma::__float_to_tf32(v.x); p[1] = wmma::__float_to_tf32(v.y);
            p[2] = wmma::__float_to_tf32(v.z); p[3] = wmma::__float_to_tf32(v.w);
        }
        #pragma unroll
        for (int it = 0; it < 4; it++) {
            int idx = tid + it * 256;
            int r = idx >> 5, c4 = idx & 31;
            float4 v = *reinterpret_cast<const float4*>(B + (size_t)(k0 + r) * F1 + col0 + c4 * 4);
            float* p = &Bs[r * LDB + c4 * 4];
            p[0] = wmma::__float_to_tf32(v.x); p[1] = wmma::__float_to_tf32(v.y);
            p[2] = wmma::__float_to_tf32(v.z); p[3] = wmma::__float_to_tf32(v.w);
        }
        __syncthreads();
        #pragma unroll
        for (int ks = 0; ks < 4; ks++) {
            wmma::fragment<wmma::matrix_a, 16, 16, 8, wmma::precision::tf32, wmma::row_major> a[2];
            wmma::fragment<wmma::matrix_b, 16, 16, 8, wmma::precision::tf32, wmma::row_major> b[4];
            #pragma unroll
            for (int i = 0; i < 2; i++)
                wmma::load_matrix_sync(a[i], &As[(wm * 32 + i * 16) * LDA + ks * 8], LDA);
            #pragma unroll
            for (int j = 0; j < 4; j++)
                wmma::load_matrix_sync(b[j], &Bs[(ks * 8) * LDB + wn * 64 + j * 16], LDB);
            #pragma unroll
            for (int i = 0; i < 2; i++)
                #pragma unroll
                for (int j = 0; j < 4; j++)
                    wmma::mma_sync(c[i][j], a[i], b[j], c[i][j]);
        }
        __syncthreads();
    }
    // epilogue: fragments -> smem -> fp16 global + partial attention logits
    #pragma unroll
    for (int i = 0; i < 2; i++)
        #pragma unroll
        for (int j = 0; j < 4; j++) {
            wmma::store_matrix_sync(&scr[warp][0], c[i][j], LDS, wmma::mem_row_major);
            __syncwarp();
            int r = row0 + wm * 32 + i * 16 + (lane >> 1);
            int cc = col0 + wn * 64 + j * 16 + (lane & 1) * 8;
            if (r < NN) {
                const float* sp = &scr[warp][(lane >> 1) * LDS + (lane & 1) * 8];
                __half2 h4[4];
                #pragma unroll
                for (int q = 0; q < 4; q++)
                    h4[q] = __floats2half2_rn(sp[2 * q], sp[2 * q + 1]);
                *reinterpret_cast<uint4*>(&g_h1h[(size_t)r * F1 + cc]) =
                    *reinterpret_cast<uint4*>(h4);
                // partial logits: 8 consecutive cols lie inside one head
                int head = cc >> 5;
                int cb = cc & 31;
                float ps = 0.f, pd = 0.f;
                #pragma unroll
                for (int q = 0; q < 8; q++) {
                    ps += sp[q] * asrc[head * HIDC + cb + q];
                    pd += sp[q] * adst[head * HIDC + cb + q];
                }
                atomicAdd(&g_als1[r * HEADS + head], ps);
                atomicAdd(&g_ald1[r * HEADS + head], pd);
            }
            __syncwarp();
        }
}

// ---------------- FP16 GEMM 2: g_h2h = out1h @ W2(fp16), fused al2 -----------
__global__ void gemm2_tc(const float* __restrict__ as2, const float* __restrict__ ad2) {
    constexpr int LDA = 80, LDB = 40, LDS = 36;   // halfs / halfs / floats
    __shared__ __half As[128 * LDA];   // 20480 B
    __shared__ __half Bs[64 * LDB];    //  5120 B
    __shared__ float  scr[4][32 * LDS];// 18432 B
    int tid = threadIdx.x;     // 128 threads, 4 warps
    int lane = tid & 31;
    int warp = tid >> 5;
    int row0 = blockIdx.y * 128;

    wmma::fragment<wmma::accumulator, 16, 16, 16, float> c[2][2];
    #pragma unroll
    for (int i = 0; i < 2; i++)
        #pragma unroll
        for (int j = 0; j < 2; j++) wmma::fill_fragment(c[i][j], 0.0f);

    for (int k0 = 0; k0 < F1; k0 += 64) {
        // A tile 128x64 halfs: 1024 uint4, 8 per thread
        #pragma unroll
        for (int it = 0; it < 8; it++) {
            int idx = tid + it * 128;
            int r = idx >> 3, c8 = idx & 7;
            *reinterpret_cast<uint4*>(&As[r * LDA + c8 * 8]) =
                *reinterpret_cast<const uint4*>(&g_out1h[(size_t)(row0 + r) * F1 + k0 + c8 * 8]);
        }
        // B tile 64x32 halfs: 256 uint4, 2 per thread
        #pragma unroll
        for (int it = 0; it < 2; it++) {
            int idx = tid + it * 128;
            int r = idx >> 2, c8 = idx & 3;
            *reinterpret_cast<uint4*>(&Bs[r * LDB + c8 * 8]) =
                *reinterpret_cast<const uint4*>(&g_w2h[(k0 + r) * HIDC + c8 * 8]);
        }
        __syncthreads();
        #pragma unroll
        for (int ks = 0; ks < 4; ks++) {
            wmma::fragment<wmma::matrix_a, 16, 16, 16, __half, wmma::row_major> a[2];
            wmma::fragment<wmma::matrix_b, 16, 16, 16, __half, wmma::row_major> b[2];
            #pragma unroll
            for (int i = 0; i < 2; i++)
                wmma::load_matrix_sync(a[i], &As[(warp * 32 + i * 16) * LDA + ks * 16], LDA);
            #pragma unroll
            for (int j = 0; j < 2; j++)
                wmma::load_matrix_sync(b[j], &Bs[(ks * 16) * LDB + j * 16], LDB);
            #pragma unroll
            for (int i = 0; i < 2; i++)
                #pragma unroll
                for (int j = 0; j < 2; j++)
                    wmma::mma_sync(c[i][j], a[i], b[j], c[i][j]);
        }
        __syncthreads();
    }
    // epilogue: fragments -> smem -> (fp16 h2 store + exact fp32 al2 logits)
    #pragma unroll
    for (int i = 0; i < 2; i++)
        #pragma unroll
        for (int j = 0; j < 2; j++)
            wmma::store_matrix_sync(&scr[warp][(i * 16) * LDS + j * 16], c[i][j], LDS,
                                    wmma::mem_row_major);
    __syncwarp();
    {
        int r = row0 + warp * 32 + lane;
        const float* sp = &scr[warp][lane * LDS];
        __half2 h2o[16];
        float ps = 0.f, pd = 0.f;
        #pragma unroll
        for (int q = 0; q < 16; q++) {
            float vx = sp[2 * q], vy = sp[2 * q + 1];
            h2o[q] = __floats2half2_rn(vx, vy);
            ps += vx * as2[2 * q] + vy * as2[2 * q + 1];
            pd += vx * ad2[2 * q] + vy * ad2[2 * q + 1];
        }
        #pragma unroll
        for (int q = 0; q < 4; q++)
            *reinterpret_cast<uint4*>(&g_h2h[(size_t)r * HIDC + q * 8]) =
                *reinterpret_cast<uint4*>(&h2o[q * 4]);
        if (r < NN) { g_als2[r] = ps; g_ald2[r] = pd; }
    }
}

// ---------------- GAT layer 1: single-pass softmax, fp16 gather --------------
__global__ void atten1_kernel(const float* __restrict__ bias) {
    __shared__ float s_w[8][32][9];   // [warp][edge-in-chunk][head] padded
    int node = (blockIdx.x * blockDim.x + threadIdx.x) >> 5;
    int lane = threadIdx.x & 31;
    int warp = (threadIdx.x >> 5) & 7;
    if (node >= NN) return;
    int start = g_rowptr[node], end = g_rowptr[node + 1];

    float ad[8];
    #pragma unroll
    for (int h = 0; h < 8; h++) ad[h] = g_ald1[node * 8 + h];

    int hsel = lane >> 4;
    float2 acc[4];
    #pragma unroll
    for (int p = 0; p < 4; p++) acc[p] = make_float2(0.f, 0.f);
    float z[8];
    #pragma unroll
    for (int h = 0; h < 8; h++) z[h] = 0.0f;
    const __half2* hbase = reinterpret_cast<const __half2*>(g_h1h);

    for (int i = start; i < end; i += 32) {
        int cnt = min(32, end - i);
        int sreg = (lane < cnt) ? g_srcs[i + lane] : 0;
        if (lane < cnt) {
            float4 a0 = *reinterpret_cast<const float4*>(g_als1 + (size_t)sreg * 8);
            float4 a1 = *reinterpret_cast<const float4*>(g_als1 + (size_t)sreg * 8 + 4);
            float av[8] = {a0.x, a0.y, a0.z, a0.w, a1.x, a1.y, a1.z, a1.w};
            #pragma unroll
            for (int h = 0; h < 8; h++) {
                float e = av[h] + ad[h];
                e = (e > 0.0f) ? e : 0.2f * e;
                float wv = __expf(e);
                s_w[warp][lane][h] = wv;
                z[h] += wv;
            }
        }
        __syncwarp();
        if (cnt == 32) {
            #pragma unroll 4
            for (int j = 0; j < 32; j++) {
                int s = __shfl_sync(FULLMASK, sreg, j);
                const __half2* hv = hbase + (size_t)s * 128 + lane;
                #pragma unroll
                for (int p = 0; p < 4; p++) {
                    float wv = s_w[warp][j][2 * p + hsel];
                    float2 f = __half22float2(hv[p * 32]);
                    acc[p].x += wv * f.x;
                    acc[p].y += wv * f.y;
                }
            }
        } else {
            #pragma unroll 4
            for (int j = 0; j < cnt; j++) {
                int s = __shfl_sync(FULLMASK, sreg, j);
                const __half2* hv = hbase + (size_t)s * 128 + lane;
                #pragma unroll
                for (int p = 0; p < 4; p++) {
                    float wv = s_w[warp][j][2 * p + hsel];
                    float2 f = __half22float2(hv[p * 32]);
                    acc[p].x += wv * f.x;
                    acc[p].y += wv * f.y;
                }
            }
        }
        __syncwarp();
    }
    // reduce z across lanes, broadcast
    float invz[8];
    #pragma unroll
    for (int h = 0; h < 8; h++) {
        float zz = z[h];
        #pragma unroll
        for (int off = 16; off; off >>= 1) zz += __shfl_down_sync(FULLMASK, zz, off);
        invz[h] = 1.0f / __shfl_sync(FULLMASK, zz, 0);
    }
    #pragma unroll
    for (int p = 0; p < 4; p++) {
        int c = p * 64 + 2 * lane;
        float iz = invz[2 * p + hsel];
        float vx = fmaxf(acc[p].x * iz + bias[c], 0.0f);
        float vy = fmaxf(acc[p].y * iz + bias[c + 1], 0.0f);
        reinterpret_cast<__half2*>(g_out1h)[(size_t)node * 128 + p * 32 + lane] =
            __floats2half2_rn(vx, vy);
    }
}

// ---------------- GAT layer 2 single-pass + fused mean-pool sums -------------
__global__ void atten2_kernel(const float* __restrict__ bias, const int* __restrict__ batch) {
    __shared__ float s_w[8][32];
    int node = (blockIdx.x * blockDim.x + threadIdx.x) >> 5;
    int lane = threadIdx.x & 31;
    int warp = (threadIdx.x >> 5) & 7;
    if (node >= NN) return;
    int start = g_rowptr[node], end = g_rowptr[node + 1];
    float ad = g_ald2[node];

    float acc = 0.0f, z = 0.0f;
    for (int i = start; i < end; i += 32) {
        int cnt = min(32, end - i);
        int sreg = (lane < cnt) ? g_srcs[i + lane] : 0;
        if (lane < cnt) {
            float e = g_als2[sreg] + ad;
            e = (e > 0.0f) ? e : 0.2f * e;
            float wv = __expf(e);
            s_w[warp][lane] = wv;
            z += wv;
        }
        __syncwarp();
        #pragma unroll 4
        for (int j = 0; j < cnt; j++) {
            int s = __shfl_sync(FULLMASK, sreg, j);
            acc += s_w[warp][j] * __half2float(g_h2h[(size_t)s * HIDC + lane]);
        }
        __syncwarp();
    }
    #pragma unroll
    for (int off = 16; off; off >>= 1) z += __shfl_down_sync(FULLMASK, z, off);
    float invz = 1.0f / __shfl_sync(FULLMASK, z, 0);

    float outv = acc * invz + bias[lane];
    atomicAdd(&g_sums[batch[node] * HIDC + lane], outv);
}

__global__ void div_kernel(float* __restrict__ out) {
    int i = blockIdx.x * blockDim.x + threadIdx.x;
    if (i < NG * HIDC)
        out[i] = g_sums[i] / fmaxf((float)g_cnts[i / HIDC], 1.0f);
}

// ---------------- launch -----------------------------------------------------
extern "C" void kernel_launch(void* const* d_in, const int* in_sizes, int n_in,
                              void* d_out, int out_size) {
    const float* x   = (const float*)d_in[0];
    const int*   ei  = (const int*)d_in[1];
    // d_in[2] edge_attr: unused by reference (lin_edge=None)
    const int* batch = (const int*)d_in[3];
    const float* W1  = (const float*)d_in[4];
    const float* as1 = (const float*)d_in[5];
    const float* ad1 = (const float*)d_in[6];
    const float* b1  = (const float*)d_in[7];
    const float* W2  = (const float*)d_in[8];
    const float* as2 = (const float*)d_in[9];
    const float* ad2 = (const float*)d_in[10];
    const float* b2  = (const float*)d_in[11];
    float* out = (float*)d_out;

    const int WB = (NN * 32 + 255) / 256;   // warp-per-node grids (6250)
    const int MB = (NN + 127) / 128;        // 391

    zero_kernel<<<(NN * HEADS + 255) / 256, 256>>>(W2);
    deg_kernel<<<EB, 256>>>(ei, batch);
    scan_blocks<<<NB_SCAN, 1024>>>();
    scan_sums<<<1, 32>>>();
    scan_apply<<<(NN + 255) / 256, 256>>>();
    fill_kernel<<<EB, 256>>>(ei);

    gemm1_tc<<<dim3(2, MB), 256>>>(x, W1, as1, ad1);
    atten1_kernel<<<WB, 256>>>(b1);

    gemm2_tc<<<dim3(1, MB), 128>>>(as2, ad2);
    atten2_kernel<<<WB, 256>>>(b2, batch);

    div_kernel<<<(NG * HIDC + 255) / 256, 256>>>(out);
}